// round 12
// baseline (speedup 1.0000x reference)
#include <cuda_runtime.h>
#include <cstdint>

// ---------------------------------------------------------------------------
// Multi-scale triplane encoder: scatter-mean of point features into 3 planes
// per scale. B=8, C=32, scales: (res=64, N=65536), (128, 32768), (256, 16384).
//
// Scatter: red.global.add.v4.f32 into channel-contiguous scratch (p,b,cell,C).
// Transpose: dense smem transpose (+count divide), MLP=4 front loads, one
// barrier (the only structure measured at ~3 TB/s on this problem).
//
// Phase overlap (same stream, 3 launches, no extra sync):
//   K1: scatter scale2                      (~22us)
//   K2: scatter scale0+1  ||  transpose scale2   (independent -> co-resident)
//   K3: transpose scale1+0
//
// Scratch invariant: g_scr/g_cnt ALL-ZERO between kernel_launch calls
// (counts zeroed by their loader thread, touched lines zeroed by predicated
// stores after the barrier). No separate zero pass ever runs.
// ---------------------------------------------------------------------------

#define BATCH 8
#define CDIM 32

#define SCR_TOTAL 66060288          // 264MB scratch (same count as output)
__device__ __align__(16) float g_scr[SCR_TOTAL];
#define CNT_TOTAL 2064384
__device__ __align__(16) float g_cnt[CNT_TOTAL];

// scale bases (floats) — same for scratch and output
#define OFF0 0
#define OFF1 (3 * 8 * 32 * 64 * 64)                 //  3,145,728
#define OFF2 (OFF1 + 3 * 8 * 32 * 128 * 128)        // 15,728,640
#define CNT0 0
#define CNT1 (3 * 8 * 64 * 64)                      //  98,304
#define CNT2 (CNT1 + 3 * 8 * 128 * 128)             // 491,520

// ---------------------------------------------------------------------------
// Index math must match XLA bit-for-bit: x/C -> x*(1/C) (f32 folded), no FMA.
// ---------------------------------------------------------------------------

__device__ __forceinline__ int grid_idx(float v, float res) {
    const float R = (float)(1.0 / (double)1.10001f);
    float u = __fadd_rn(__fmul_rn(v, R), 0.5f);       // no fma contraction
    u = fminf(fmaxf(u, 0.0f), 0.99999f);
    return (int)(__fmul_rn(u, res));
}

__device__ __forceinline__ void red_v4(float* p, float a, float b, float c, float d) {
    asm volatile("red.global.add.v4.f32 [%0], {%1, %2, %3, %4};"
                 :: "l"(p), "f"(a), "f"(b), "f"(c), "f"(d)
                 : "memory");
}

template <int RES, int LOGN>
__device__ __forceinline__ void scatter_body(const float* __restrict__ f,
                                             const float* __restrict__ cd,
                                             int scr_off, int cnt_off, int gid) {
    const int R2 = RES * RES;
    int b = gid >> LOGN;

    float4 feat[CDIM / 4];
    const float4* fv = reinterpret_cast<const float4*>(f + (size_t)gid * CDIM);
#pragma unroll
    for (int i = 0; i < CDIM / 4; i++) feat[i] = fv[i];
    float x = cd[gid * 3 + 0];
    float y = cd[gid * 3 + 1];
    float z = cd[gid * 3 + 2];

    int gx = grid_idx(x, (float)RES);
    int gy = grid_idx(y, (float)RES);
    int gz = grid_idx(z, (float)RES);

    int idx[3];
    idx[0] = gx + RES * gz;   // xz
    idx[1] = gx + RES * gy;   // xy
    idx[2] = gy + RES * gz;   // yz

#pragma unroll
    for (int p = 0; p < 3; p++) {
        atomicAdd(&g_cnt[cnt_off + ((size_t)p * BATCH + b) * R2 + idx[p]], 1.0f);
        float* o = g_scr + scr_off +
                   (((size_t)p * BATCH + b) * R2 + idx[p]) * CDIM;  // 128B line
#pragma unroll
        for (int i = 0; i < CDIM / 4; i++) {
            red_v4(o + 4 * i, feat[i].x, feat[i].y, feat[i].z, feat[i].w);
        }
    }
}

// ---------------------------------------------------------------------------
// Dense transpose body: MLP=4 front loads, one barrier. Caller provides smem.
// ---------------------------------------------------------------------------

struct TBuf {
    float tile[32][33];
    float scnt[32];
    float crec[32];
};

template <int RES>
__device__ __forceinline__ void dense_body(float* __restrict__ out,
                                           int scr_off, int cnt_off,
                                           int tile_idx, int b, int p,
                                           int tx, int ty, TBuf* sb) {
    const int R2 = RES * RES;
    int cell0 = tile_idx * 32;

    size_t base = ((size_t)p * BATCH + b) * R2;
    float* cnt = g_cnt + cnt_off + base + cell0;
    float* src = g_scr + scr_off + (base + cell0) * CDIM;

    float v[4];
#pragma unroll
    for (int k = 0; k < 4; k++) v[k] = src[(size_t)(ty + 8 * k) * CDIM + tx];

    if (ty == 0) {
        float c = cnt[tx];
        cnt[tx] = 0.0f;                       // restore count invariant
        sb->scnt[tx] = c;
        sb->crec[tx] = __frcp_rn(fmaxf(c, 1.0f));
    }

#pragma unroll
    for (int k = 0; k < 4; k++) sb->tile[ty + 8 * k][tx] = v[k];
    __syncthreads();

#pragma unroll
    for (int k = 0; k < 4; k++) {
        int row = ty + 8 * k;
        if (sb->scnt[row] != 0.0f) src[(size_t)row * CDIM + tx] = 0.0f;
    }

    float* dst = out + base * CDIM + cell0;
    float r = sb->crec[tx];
#pragma unroll
    for (int k = 0; k < 4; k++) {
        int ch = ty + 8 * k;
        dst[(size_t)ch * R2 + tx] = __fmul_rn(sb->tile[tx][ch], r);
    }
}

// ---------------------------------------------------------------------------
// K1: scatter scale2 (512 blocks)
// ---------------------------------------------------------------------------
__global__ __launch_bounds__(256)
void k1_scatter2(const float* __restrict__ f2, const float* __restrict__ c2) {
    scatter_body<256, 14>(f2, c2, OFF2, CNT2, blockIdx.x * 256 + threadIdx.x);
}

// ---------------------------------------------------------------------------
// K2: scatter scale0 [0,2048) + scale1 [2048,3072)  ||  transpose scale2
//     [3072, 3072+49152). Scatter blocks first so they start in wave 1.
// ---------------------------------------------------------------------------
#define K2_TOTAL (3072 + 49152)

__global__ __launch_bounds__(256)
void k2_mixed(const float* __restrict__ f0, const float* __restrict__ c0,
              const float* __restrict__ f1, const float* __restrict__ c1,
              float* __restrict__ out) {
    __shared__ TBuf sb;
    int blk = blockIdx.x;
    int t = threadIdx.x;
    if (blk < 2048) {
        scatter_body<64, 16>(f0, c0, OFF0, CNT0, blk * 256 + t);
    } else if (blk < 3072) {
        scatter_body<128, 15>(f1, c1, OFF1, CNT1, (blk - 2048) * 256 + t);
    } else {
        int q = blk - 3072;
        int tile = q & 2047, bp = q >> 11;      // 2048 tiles, 24 (b,p)
        dense_body<256>(out + OFF2, OFF2, CNT2, tile, bp & 7, bp >> 3,
                        t & 31, t >> 5, &sb);
    }
}

// ---------------------------------------------------------------------------
// K3: transpose scale1 [0,12288) + scale0 [12288,15360)
// ---------------------------------------------------------------------------
#define K3_TOTAL (12288 + 3072)

__global__ __launch_bounds__(256)
void k3_transpose01(float* __restrict__ out) {
    __shared__ TBuf sb;
    int blk = blockIdx.x;
    int t = threadIdx.x;
    if (blk < 12288) {
        int tile = blk & 511, bp = blk >> 9;
        dense_body<128>(out + OFF1, OFF1, CNT1, tile, bp & 7, bp >> 3,
                        t & 31, t >> 5, &sb);
    } else {
        int q = blk - 12288;
        int tile = q & 127, bp = q >> 7;
        dense_body<64>(out + OFF0, OFF0, CNT0, tile, bp & 7, bp >> 3,
                       t & 31, t >> 5, &sb);
    }
}

// ---------------------------------------------------------------------------

extern "C" void kernel_launch(void* const* d_in, const int* in_sizes, int n_in,
                              void* d_out, int out_size) {
    // Match inputs by element count (all six are distinct).
    const float *f0 = nullptr, *f1 = nullptr, *f2 = nullptr;
    const float *c0 = nullptr, *c1 = nullptr, *c2 = nullptr;
    for (int i = 0; i < n_in; i++) {
        int s = in_sizes[i];
        const float* p = (const float*)d_in[i];
        if (s == 8 * 65536 * 32) f0 = p;
        else if (s == 8 * 32768 * 32) f1 = p;
        else if (s == 8 * 16384 * 32) f2 = p;
        else if (s == 8 * 65536 * 3) c0 = p;
        else if (s == 8 * 32768 * 3) c1 = p;
        else if (s == 8 * 16384 * 3) c2 = p;
    }

    float* out = (float*)d_out;

    k1_scatter2<<<512, 256>>>(f2, c2);                         // scatter s2
    k2_mixed<<<K2_TOTAL, 256>>>(f0, c0, f1, c1, out);          // s0+s1 || t2
    k3_transpose01<<<K3_TOTAL, 256>>>(out);                    // t1+t0
}

// round 13
// speedup vs baseline: 1.0493x; 1.0493x over previous
#include <cuda_runtime.h>
#include <cstdint>

// ---------------------------------------------------------------------------
// Multi-scale triplane encoder: scatter-mean of point features into 3 planes
// per scale. B=8, C=32, scales: (res=64, N=65536), (128, 32768), (256, 16384).
//
// Serial two-phase (overlap thrashes L2; measured):
//   scatter_all:  red.global.add.v4.f32 into channel-contiguous scratch
//                 (p,b,cell,C), counts into g_cnt.
//   transpose_all: dense 64-cell smem transpose (+count divide), 8 front-
//                 batched independent scalar loads per thread (MLP=8), ONE
//                 barrier — the only structure measured at ~3 TB/s here.
//
// Scratch invariant: g_scr/g_cnt ALL-ZERO between kernel_launch calls
// (counts zeroed by their loader thread, touched lines zeroed by predicated
// stores after the barrier). No separate zero pass ever runs.
// ---------------------------------------------------------------------------

#define BATCH 8
#define CDIM 32

#define SCR_TOTAL 66060288          // 264MB scratch (same count as output)
__device__ __align__(16) float g_scr[SCR_TOTAL];
#define CNT_TOTAL 2064384
__device__ __align__(16) float g_cnt[CNT_TOTAL];

// scale bases (floats) — same for scratch and output
#define OFF0 0
#define OFF1 (3 * 8 * 32 * 64 * 64)                 //  3,145,728
#define OFF2 (OFF1 + 3 * 8 * 32 * 128 * 128)        // 15,728,640
#define CNT0 0
#define CNT1 (3 * 8 * 64 * 64)                      //  98,304
#define CNT2 (CNT1 + 3 * 8 * 128 * 128)             // 491,520

// ---------------------------------------------------------------------------
// Index math must match XLA bit-for-bit: x/C -> x*(1/C) (f32 folded), no FMA.
// ---------------------------------------------------------------------------

__device__ __forceinline__ int grid_idx(float v, float res) {
    const float R = (float)(1.0 / (double)1.10001f);
    float u = __fadd_rn(__fmul_rn(v, R), 0.5f);       // no fma contraction
    u = fminf(fmaxf(u, 0.0f), 0.99999f);
    return (int)(__fmul_rn(u, res));
}

__device__ __forceinline__ void red_v4(float* p, float a, float b, float c, float d) {
    asm volatile("red.global.add.v4.f32 [%0], {%1, %2, %3, %4};"
                 :: "l"(p), "f"(a), "f"(b), "f"(c), "f"(d)
                 : "memory");
}

template <int RES, int LOGN>
__device__ __forceinline__ void scatter_body(const float* __restrict__ f,
                                             const float* __restrict__ cd,
                                             int scr_off, int cnt_off, int gid) {
    const int R2 = RES * RES;
    int b = gid >> LOGN;

    float4 feat[CDIM / 4];
    const float4* fv = reinterpret_cast<const float4*>(f + (size_t)gid * CDIM);
#pragma unroll
    for (int i = 0; i < CDIM / 4; i++) feat[i] = fv[i];
    float x = cd[gid * 3 + 0];
    float y = cd[gid * 3 + 1];
    float z = cd[gid * 3 + 2];

    int gx = grid_idx(x, (float)RES);
    int gy = grid_idx(y, (float)RES);
    int gz = grid_idx(z, (float)RES);

    int idx[3];
    idx[0] = gx + RES * gz;   // xz
    idx[1] = gx + RES * gy;   // xy
    idx[2] = gy + RES * gz;   // yz

#pragma unroll
    for (int p = 0; p < 3; p++) {
        atomicAdd(&g_cnt[cnt_off + ((size_t)p * BATCH + b) * R2 + idx[p]], 1.0f);
        float* o = g_scr + scr_off +
                   (((size_t)p * BATCH + b) * R2 + idx[p]) * CDIM;  // 128B line
#pragma unroll
        for (int i = 0; i < CDIM / 4; i++) {
            red_v4(o + 4 * i, feat[i].x, feat[i].y, feat[i].z, feat[i].w);
        }
    }
}

// merged scatter: blocks [0,2048) scale0, [2048,3072) scale1, [3072,3584) scale2
__global__ __launch_bounds__(256)
void scatter_all_kernel(const float* __restrict__ f0, const float* __restrict__ c0,
                        const float* __restrict__ f1, const float* __restrict__ c1,
                        const float* __restrict__ f2, const float* __restrict__ c2) {
    int blk = blockIdx.x;
    int t = threadIdx.x;
    if (blk < 2048) {
        scatter_body<64, 16>(f0, c0, OFF0, CNT0, blk * 256 + t);
    } else if (blk < 3072) {
        scatter_body<128, 15>(f1, c1, OFF1, CNT1, (blk - 2048) * 256 + t);
    } else {
        scatter_body<256, 14>(f2, c2, OFF2, CNT2, (blk - 3072) * 256 + t);
    }
}

// ---------------------------------------------------------------------------
// Dense 64-cell transpose body: 8 independent front-batched scalar loads
// (MLP=8), counts loaded in parallel by warps ty=0/1, ONE barrier,
// predicated zero-restore after the barrier, 8 coalesced output stores.
// ---------------------------------------------------------------------------

template <int RES>
__device__ __forceinline__ void dense64_body(float* __restrict__ out,
                                             int scr_off, int cnt_off,
                                             int tile_idx, int b, int p) {
    const int R2 = RES * RES;
    __shared__ float tile[64][33];
    __shared__ float scnt[64];
    __shared__ float crec[64];
    int tx = threadIdx.x, ty = threadIdx.y;
    int cell0 = tile_idx * 64;

    size_t base = ((size_t)p * BATCH + b) * R2;
    float* cnt = g_cnt + cnt_off + base + cell0;
    float* src = g_scr + scr_off + (base + cell0) * CDIM;

    // 8 independent loads, front-batched
    float v[8];
#pragma unroll
    for (int k = 0; k < 8; k++) v[k] = src[(size_t)(ty + 8 * k) * CDIM + tx];

    // counts: warps ty=0,1 handle cells [0,32) and [32,64)
    if (ty < 2) {
        int cell = ty * 32 + tx;
        float c = cnt[cell];
        cnt[cell] = 0.0f;                     // restore count invariant
        scnt[cell] = c;
        crec[cell] = __frcp_rn(fmaxf(c, 1.0f));
    }

#pragma unroll
    for (int k = 0; k < 8; k++) tile[ty + 8 * k][tx] = v[k];
    __syncthreads();

    // predicated zero-restore of touched lines (off the load path)
#pragma unroll
    for (int k = 0; k < 8; k++) {
        int row = ty + 8 * k;
        if (scnt[row] != 0.0f) src[(size_t)row * CDIM + tx] = 0.0f;
    }

    // output: 32 channels x 64 cells; thread -> (ch=ty+8k, cells tx & 32+tx)
    float* dst = out + base * CDIM + cell0;
    float r0 = crec[tx];
    float r1 = crec[32 + tx];
#pragma unroll
    for (int k = 0; k < 4; k++) {
        int ch = ty + 8 * k;
        dst[(size_t)ch * R2 + tx]      = __fmul_rn(tile[tx][ch], r0);
        dst[(size_t)ch * R2 + 32 + tx] = __fmul_rn(tile[32 + tx][ch], r1);
    }
}

// merged transpose: flat grid decodes (scale, tile, b, p)
// scale2: 1024 tiles * 24 = 24576; scale1: 256*24 = 6144; scale0: 64*24 = 1536
#define TRA 24576
#define TRB (TRA + 6144)
#define TR_TOTAL (TRB + 1536)

__global__ __launch_bounds__(256)
void transpose_all_kernel(float* __restrict__ out) {
    int blk = blockIdx.x;
    if (blk < TRA) {
        int tile = blk & 1023, bp = blk >> 10;
        dense64_body<256>(out + OFF2, OFF2, CNT2, tile, bp & 7, bp >> 3);
    } else if (blk < TRB) {
        int q = blk - TRA;
        int tile = q & 255, bp = q >> 8;
        dense64_body<128>(out + OFF1, OFF1, CNT1, tile, bp & 7, bp >> 3);
    } else {
        int q = blk - TRB;
        int tile = q & 63, bp = q >> 6;
        dense64_body<64>(out + OFF0, OFF0, CNT0, tile, bp & 7, bp >> 3);
    }
}

// ---------------------------------------------------------------------------

extern "C" void kernel_launch(void* const* d_in, const int* in_sizes, int n_in,
                              void* d_out, int out_size) {
    // Match inputs by element count (all six are distinct).
    const float *f0 = nullptr, *f1 = nullptr, *f2 = nullptr;
    const float *c0 = nullptr, *c1 = nullptr, *c2 = nullptr;
    for (int i = 0; i < n_in; i++) {
        int s = in_sizes[i];
        const float* p = (const float*)d_in[i];
        if (s == 8 * 65536 * 32) f0 = p;
        else if (s == 8 * 32768 * 32) f1 = p;
        else if (s == 8 * 16384 * 32) f2 = p;
        else if (s == 8 * 65536 * 3) c0 = p;
        else if (s == 8 * 32768 * 3) c1 = p;
        else if (s == 8 * 16384 * 3) c2 = p;
    }

    float* out = (float*)d_out;

    // scatter all scales (scratch all-zero on entry by invariant)
    scatter_all_kernel<<<3584, 256>>>(f0, c0, f1, c1, f2, c2);

    // transpose + divide into d_out; restores scratch/count zeros
    transpose_all_kernel<<<TR_TOTAL, dim3(32, 8)>>>(out);
}

// round 14
// speedup vs baseline: 1.2294x; 1.1716x over previous
#include <cuda_runtime.h>
#include <cstdint>

// ---------------------------------------------------------------------------
// Multi-scale triplane encoder: scatter-mean of point features into 3 planes
// per scale. B=8, C=32, scales: (res=64, N=65536), (128, 32768), (256, 16384).
//
// Phase 1 scatter: red.global.add.v4.f32 into channel-contiguous scratch
//   (p,b,cell,C), counts into g_cnt.  (L2-atomic-rate bound.)
// Phase 2 transpose: dense 128-cell smem transpose (+count divide).
//   4 independent front-batched LDG.128 per thread (64B in flight per thread
//   at 4 L1tex queue entries), counts loaded in parallel by 32 threads,
//   ONE barrier, predicated zero-restore after the barrier.
//
// Scratch invariant: g_scr/g_cnt ALL-ZERO between kernel_launch calls
// (counts zeroed by their loader thread, touched lines zeroed by predicated
// stores after the barrier). No separate zero pass ever runs.
// ---------------------------------------------------------------------------

#define BATCH 8
#define CDIM 32

#define SCR_TOTAL 66060288          // 264MB scratch (same count as output)
__device__ __align__(16) float g_scr[SCR_TOTAL];
#define CNT_TOTAL 2064384
__device__ __align__(16) float g_cnt[CNT_TOTAL];

// scale bases (floats) — same for scratch and output
#define OFF0 0
#define OFF1 (3 * 8 * 32 * 64 * 64)                 //  3,145,728
#define OFF2 (OFF1 + 3 * 8 * 32 * 128 * 128)        // 15,728,640
#define CNT0 0
#define CNT1 (3 * 8 * 64 * 64)                      //  98,304
#define CNT2 (CNT1 + 3 * 8 * 128 * 128)             // 491,520

// ---------------------------------------------------------------------------
// Index math must match XLA bit-for-bit: x/C -> x*(1/C) (f32 folded), no FMA.
// ---------------------------------------------------------------------------

__device__ __forceinline__ int grid_idx(float v, float res) {
    const float R = (float)(1.0 / (double)1.10001f);
    float u = __fadd_rn(__fmul_rn(v, R), 0.5f);       // no fma contraction
    u = fminf(fmaxf(u, 0.0f), 0.99999f);
    return (int)(__fmul_rn(u, res));
}

__device__ __forceinline__ void red_v4(float* p, float a, float b, float c, float d) {
    asm volatile("red.global.add.v4.f32 [%0], {%1, %2, %3, %4};"
                 :: "l"(p), "f"(a), "f"(b), "f"(c), "f"(d)
                 : "memory");
}

template <int RES, int LOGN>
__device__ __forceinline__ void scatter_body(const float* __restrict__ f,
                                             const float* __restrict__ cd,
                                             int scr_off, int cnt_off, int gid) {
    const int R2 = RES * RES;
    int b = gid >> LOGN;

    float4 feat[CDIM / 4];
    const float4* fv = reinterpret_cast<const float4*>(f + (size_t)gid * CDIM);
#pragma unroll
    for (int i = 0; i < CDIM / 4; i++) feat[i] = fv[i];
    float x = cd[gid * 3 + 0];
    float y = cd[gid * 3 + 1];
    float z = cd[gid * 3 + 2];

    int gx = grid_idx(x, (float)RES);
    int gy = grid_idx(y, (float)RES);
    int gz = grid_idx(z, (float)RES);

    int idx[3];
    idx[0] = gx + RES * gz;   // xz
    idx[1] = gx + RES * gy;   // xy
    idx[2] = gy + RES * gz;   // yz

#pragma unroll
    for (int p = 0; p < 3; p++) {
        atomicAdd(&g_cnt[cnt_off + ((size_t)p * BATCH + b) * R2 + idx[p]], 1.0f);
        float* o = g_scr + scr_off +
                   (((size_t)p * BATCH + b) * R2 + idx[p]) * CDIM;  // 128B line
#pragma unroll
        for (int i = 0; i < CDIM / 4; i++) {
            red_v4(o + 4 * i, feat[i].x, feat[i].y, feat[i].z, feat[i].w);
        }
    }
}

// merged scatter: blocks [0,2048) scale0, [2048,3072) scale1, [3072,3584) scale2
__global__ __launch_bounds__(256)
void scatter_all_kernel(const float* __restrict__ f0, const float* __restrict__ c0,
                        const float* __restrict__ f1, const float* __restrict__ c1,
                        const float* __restrict__ f2, const float* __restrict__ c2) {
    int blk = blockIdx.x;
    int t = threadIdx.x;
    if (blk < 2048) {
        scatter_body<64, 16>(f0, c0, OFF0, CNT0, blk * 256 + t);
    } else if (blk < 3072) {
        scatter_body<128, 15>(f1, c1, OFF1, CNT1, (blk - 2048) * 256 + t);
    } else {
        scatter_body<256, 14>(f2, c2, OFF2, CNT2, (blk - 3072) * 256 + t);
    }
}

// ---------------------------------------------------------------------------
// Dense 128-cell transpose body. 256 threads.
//  Loads:  thread t: cl=t>>3, q=t&7; 4 independent LDG.128 of
//          src[(cl+32k)*32 + 4q], k=0..3  (front-batched).
//  Counts: threads t<32 load one float4 of counts each, zero them,
//          compute 4 reciprocals (parallel with the data loads).
//  ONE __syncthreads.
//  Restore: predicated STG.128 zeros per touched cell line.
//  Output: thread t: ch=t>>3, u=t&7; 4 coalesced STG.128 of
//          dst[ch*R2 + cell0 + 32k + 4u].
// ---------------------------------------------------------------------------

template <int RES>
__device__ __forceinline__ void dense128_body(float* __restrict__ out,
                                              int scr_off, int cnt_off,
                                              int tile_idx, int b, int p) {
    const int R2 = RES * RES;
    __shared__ float tile[128][33];
    __shared__ float scnt[128];
    __shared__ float crec[128];
    int t = threadIdx.x;
    int cell0 = tile_idx * 128;

    size_t base = ((size_t)p * BATCH + b) * R2;
    float* cnt = g_cnt + cnt_off + base + cell0;
    float4* srcv = reinterpret_cast<float4*>(g_scr + scr_off + (base + cell0) * CDIM);

    int cl = t >> 3, q = t & 7;

    // 4 independent vector loads, front-batched
    float4 v[4];
#pragma unroll
    for (int k = 0; k < 4; k++) v[k] = srcv[(size_t)(cl + 32 * k) * 8 + q];

    // counts in parallel (32 threads x float4)
    if (t < 32) {
        float4 cv = reinterpret_cast<const float4*>(cnt)[t];
        reinterpret_cast<float4*>(cnt)[t] = make_float4(0.f, 0.f, 0.f, 0.f);
        scnt[4 * t + 0] = cv.x;  crec[4 * t + 0] = __frcp_rn(fmaxf(cv.x, 1.0f));
        scnt[4 * t + 1] = cv.y;  crec[4 * t + 1] = __frcp_rn(fmaxf(cv.y, 1.0f));
        scnt[4 * t + 2] = cv.z;  crec[4 * t + 2] = __frcp_rn(fmaxf(cv.z, 1.0f));
        scnt[4 * t + 3] = cv.w;  crec[4 * t + 3] = __frcp_rn(fmaxf(cv.w, 1.0f));
    }

#pragma unroll
    for (int k = 0; k < 4; k++) {
        int row = cl + 32 * k;
        tile[row][4 * q + 0] = v[k].x;
        tile[row][4 * q + 1] = v[k].y;
        tile[row][4 * q + 2] = v[k].z;
        tile[row][4 * q + 3] = v[k].w;
    }
    __syncthreads();

    // predicated zero-restore of touched lines (off the load path)
#pragma unroll
    for (int k = 0; k < 4; k++) {
        int row = cl + 32 * k;
        if (scnt[row] != 0.0f)
            srcv[(size_t)row * 8 + q] = make_float4(0.f, 0.f, 0.f, 0.f);
    }

    // output: ch = t>>3, cell quad u = t&7; 4 vector stores
    int ch = t >> 3, u = t & 7;
    float4* dstv = reinterpret_cast<float4*>(out + base * CDIM + (size_t)ch * R2 + cell0);
#pragma unroll
    for (int k = 0; k < 4; k++) {
        int c0 = 32 * k + 4 * u;
        float4 o;
        o.x = __fmul_rn(tile[c0 + 0][ch], crec[c0 + 0]);
        o.y = __fmul_rn(tile[c0 + 1][ch], crec[c0 + 1]);
        o.z = __fmul_rn(tile[c0 + 2][ch], crec[c0 + 2]);
        o.w = __fmul_rn(tile[c0 + 3][ch], crec[c0 + 3]);
        dstv[8 * k + u] = o;
    }
}

// merged transpose: flat grid decodes (scale, tile, b, p)
// scale2: 512 tiles * 24 = 12288; scale1: 128*24 = 3072; scale0: 32*24 = 768
#define TRA 12288
#define TRB (TRA + 3072)
#define TR_TOTAL (TRB + 768)

__global__ __launch_bounds__(256)
void transpose_all_kernel(float* __restrict__ out) {
    int blk = blockIdx.x;
    if (blk < TRA) {
        int tile = blk & 511, bp = blk >> 9;
        dense128_body<256>(out + OFF2, OFF2, CNT2, tile, bp & 7, bp >> 3);
    } else if (blk < TRB) {
        int q = blk - TRA;
        int tile = q & 127, bp = q >> 7;
        dense128_body<128>(out + OFF1, OFF1, CNT1, tile, bp & 7, bp >> 3);
    } else {
        int q = blk - TRB;
        int tile = q & 31, bp = q >> 5;
        dense128_body<64>(out + OFF0, OFF0, CNT0, tile, bp & 7, bp >> 3);
    }
}

// ---------------------------------------------------------------------------

extern "C" void kernel_launch(void* const* d_in, const int* in_sizes, int n_in,
                              void* d_out, int out_size) {
    // Match inputs by element count (all six are distinct).
    const float *f0 = nullptr, *f1 = nullptr, *f2 = nullptr;
    const float *c0 = nullptr, *c1 = nullptr, *c2 = nullptr;
    for (int i = 0; i < n_in; i++) {
        int s = in_sizes[i];
        const float* p = (const float*)d_in[i];
        if (s == 8 * 65536 * 32) f0 = p;
        else if (s == 8 * 32768 * 32) f1 = p;
        else if (s == 8 * 16384 * 32) f2 = p;
        else if (s == 8 * 65536 * 3) c0 = p;
        else if (s == 8 * 32768 * 3) c1 = p;
        else if (s == 8 * 16384 * 3) c2 = p;
    }

    float* out = (float*)d_out;

    // scatter all scales (scratch all-zero on entry by invariant)
    scatter_all_kernel<<<3584, 256>>>(f0, c0, f1, c1, f2, c2);

    // transpose + divide into d_out; restores scratch/count zeros
    transpose_all_kernel<<<TR_TOTAL, 256>>>(out);
}

// round 15
// speedup vs baseline: 1.2562x; 1.0218x over previous
#include <cuda_runtime.h>
#include <cstdint>

// ---------------------------------------------------------------------------
// Multi-scale triplane encoder: scatter-mean of point features into 3 planes
// per scale. B=8, C=32, scales: (res=64, N=65536), (128, 32768), (256, 16384).
//
// Three launches with L2-compatible overlap:
//   K1: scatter scale0+1 (accumulation set 63MB, L2-resident)
//   K2: scatter scale2 (42MB touched RMW)  ||  transpose scale0+1
//       (reads L2-warm scratch; combined hot set ~105MB < L2)
//   K3: transpose scale2
//
// Scatter: red.global.add.v4.f32 into channel-contiguous scratch (p,b,cell,C).
// Transpose: dense 128-cell smem transpose, 4 independent front-batched
// LDG.128 per thread, counts loaded in parallel, ONE barrier, predicated
// zero-restore after the barrier  (R14 body, measured 3.75 TB/s).
//
// Scratch invariant: g_scr/g_cnt ALL-ZERO between kernel_launch calls.
// ---------------------------------------------------------------------------

#define BATCH 8
#define CDIM 32

#define SCR_TOTAL 66060288          // 264MB scratch (same count as output)
__device__ __align__(16) float g_scr[SCR_TOTAL];
#define CNT_TOTAL 2064384
__device__ __align__(16) float g_cnt[CNT_TOTAL];

// scale bases (floats) — same for scratch and output
#define OFF0 0
#define OFF1 (3 * 8 * 32 * 64 * 64)                 //  3,145,728
#define OFF2 (OFF1 + 3 * 8 * 32 * 128 * 128)        // 15,728,640
#define CNT0 0
#define CNT1 (3 * 8 * 64 * 64)                      //  98,304
#define CNT2 (CNT1 + 3 * 8 * 128 * 128)             // 491,520

// ---------------------------------------------------------------------------
// Index math must match XLA bit-for-bit: x/C -> x*(1/C) (f32 folded), no FMA.
// ---------------------------------------------------------------------------

__device__ __forceinline__ int grid_idx(float v, float res) {
    const float R = (float)(1.0 / (double)1.10001f);
    float u = __fadd_rn(__fmul_rn(v, R), 0.5f);       // no fma contraction
    u = fminf(fmaxf(u, 0.0f), 0.99999f);
    return (int)(__fmul_rn(u, res));
}

__device__ __forceinline__ void red_v4(float* p, float a, float b, float c, float d) {
    asm volatile("red.global.add.v4.f32 [%0], {%1, %2, %3, %4};"
                 :: "l"(p), "f"(a), "f"(b), "f"(c), "f"(d)
                 : "memory");
}

template <int RES, int LOGN>
__device__ __forceinline__ void scatter_body(const float* __restrict__ f,
                                             const float* __restrict__ cd,
                                             int scr_off, int cnt_off, int gid) {
    const int R2 = RES * RES;
    int b = gid >> LOGN;

    float4 feat[CDIM / 4];
    const float4* fv = reinterpret_cast<const float4*>(f + (size_t)gid * CDIM);
#pragma unroll
    for (int i = 0; i < CDIM / 4; i++) feat[i] = fv[i];
    float x = cd[gid * 3 + 0];
    float y = cd[gid * 3 + 1];
    float z = cd[gid * 3 + 2];

    int gx = grid_idx(x, (float)RES);
    int gy = grid_idx(y, (float)RES);
    int gz = grid_idx(z, (float)RES);

    int idx[3];
    idx[0] = gx + RES * gz;   // xz
    idx[1] = gx + RES * gy;   // xy
    idx[2] = gy + RES * gz;   // yz

#pragma unroll
    for (int p = 0; p < 3; p++) {
        atomicAdd(&g_cnt[cnt_off + ((size_t)p * BATCH + b) * R2 + idx[p]], 1.0f);
        float* o = g_scr + scr_off +
                   (((size_t)p * BATCH + b) * R2 + idx[p]) * CDIM;  // 128B line
#pragma unroll
        for (int i = 0; i < CDIM / 4; i++) {
            red_v4(o + 4 * i, feat[i].x, feat[i].y, feat[i].z, feat[i].w);
        }
    }
}

// ---------------------------------------------------------------------------
// Dense 128-cell transpose body (R14, measured 3.75 TB/s). 256 threads.
// ---------------------------------------------------------------------------

template <int RES>
__device__ __forceinline__ void dense128_body(float* __restrict__ out,
                                              int scr_off, int cnt_off,
                                              int tile_idx, int b, int p) {
    const int R2 = RES * RES;
    __shared__ float tile[128][33];
    __shared__ float scnt[128];
    __shared__ float crec[128];
    int t = threadIdx.x;
    int cell0 = tile_idx * 128;

    size_t base = ((size_t)p * BATCH + b) * R2;
    float* cnt = g_cnt + cnt_off + base + cell0;
    float4* srcv = reinterpret_cast<float4*>(g_scr + scr_off + (base + cell0) * CDIM);

    int cl = t >> 3, q = t & 7;

    // 4 independent vector loads, front-batched
    float4 v[4];
#pragma unroll
    for (int k = 0; k < 4; k++) v[k] = srcv[(size_t)(cl + 32 * k) * 8 + q];

    // counts in parallel (32 threads x float4)
    if (t < 32) {
        float4 cv = reinterpret_cast<const float4*>(cnt)[t];
        reinterpret_cast<float4*>(cnt)[t] = make_float4(0.f, 0.f, 0.f, 0.f);
        scnt[4 * t + 0] = cv.x;  crec[4 * t + 0] = __frcp_rn(fmaxf(cv.x, 1.0f));
        scnt[4 * t + 1] = cv.y;  crec[4 * t + 1] = __frcp_rn(fmaxf(cv.y, 1.0f));
        scnt[4 * t + 2] = cv.z;  crec[4 * t + 2] = __frcp_rn(fmaxf(cv.z, 1.0f));
        scnt[4 * t + 3] = cv.w;  crec[4 * t + 3] = __frcp_rn(fmaxf(cv.w, 1.0f));
    }

#pragma unroll
    for (int k = 0; k < 4; k++) {
        int row = cl + 32 * k;
        tile[row][4 * q + 0] = v[k].x;
        tile[row][4 * q + 1] = v[k].y;
        tile[row][4 * q + 2] = v[k].z;
        tile[row][4 * q + 3] = v[k].w;
    }
    __syncthreads();

    // predicated zero-restore of touched lines (off the load path)
#pragma unroll
    for (int k = 0; k < 4; k++) {
        int row = cl + 32 * k;
        if (scnt[row] != 0.0f)
            srcv[(size_t)row * 8 + q] = make_float4(0.f, 0.f, 0.f, 0.f);
    }

    // output: ch = t>>3, cell quad u = t&7; 4 vector stores
    int ch = t >> 3, u = t & 7;
    float4* dstv = reinterpret_cast<float4*>(out + base * CDIM + (size_t)ch * R2 + cell0);
#pragma unroll
    for (int k = 0; k < 4; k++) {
        int c0 = 32 * k + 4 * u;
        float4 o;
        o.x = __fmul_rn(tile[c0 + 0][ch], crec[c0 + 0]);
        o.y = __fmul_rn(tile[c0 + 1][ch], crec[c0 + 1]);
        o.z = __fmul_rn(tile[c0 + 2][ch], crec[c0 + 2]);
        o.w = __fmul_rn(tile[c0 + 3][ch], crec[c0 + 3]);
        dstv[8 * k + u] = o;
    }
}

// ---------------------------------------------------------------------------
// K1: scatter scale0 [0,2048) + scale1 [2048,3072)
// ---------------------------------------------------------------------------
__global__ __launch_bounds__(256)
void k1_scatter01(const float* __restrict__ f0, const float* __restrict__ c0,
                  const float* __restrict__ f1, const float* __restrict__ c1) {
    int blk = blockIdx.x;
    int t = threadIdx.x;
    if (blk < 2048) {
        scatter_body<64, 16>(f0, c0, OFF0, CNT0, blk * 256 + t);
    } else {
        scatter_body<128, 15>(f1, c1, OFF1, CNT1, (blk - 2048) * 256 + t);
    }
}

// ---------------------------------------------------------------------------
// K2: scatter scale2 [0,512)  ||  transpose scale1 [512,512+3072) +
//     scale0 [3584, 3584+768).  Scatter blocks first -> wave 1.
// ---------------------------------------------------------------------------
#define K2_TOTAL (512 + 3072 + 768)

__global__ __launch_bounds__(256)
void k2_mixed(const float* __restrict__ f2, const float* __restrict__ c2,
              float* __restrict__ out) {
    int blk = blockIdx.x;
    if (blk < 512) {
        scatter_body<256, 14>(f2, c2, OFF2, CNT2, blk * 256 + (int)threadIdx.x);
    } else if (blk < 512 + 3072) {
        int q = blk - 512;
        int tile = q & 127, bp = q >> 7;          // 128 tiles, 24 (b,p)
        dense128_body<128>(out + OFF1, OFF1, CNT1, tile, bp & 7, bp >> 3);
    } else {
        int q = blk - (512 + 3072);
        int tile = q & 31, bp = q >> 5;           // 32 tiles, 24 (b,p)
        dense128_body<64>(out + OFF0, OFF0, CNT0, tile, bp & 7, bp >> 3);
    }
}

// ---------------------------------------------------------------------------
// K3: transpose scale2 (512 tiles * 24 = 12288 blocks)
// ---------------------------------------------------------------------------
__global__ __launch_bounds__(256)
void k3_transpose2(float* __restrict__ out) {
    int blk = blockIdx.x;
    int tile = blk & 511, bp = blk >> 9;
    dense128_body<256>(out + OFF2, OFF2, CNT2, tile, bp & 7, bp >> 3);
}

// ---------------------------------------------------------------------------

extern "C" void kernel_launch(void* const* d_in, const int* in_sizes, int n_in,
                              void* d_out, int out_size) {
    // Match inputs by element count (all six are distinct).
    const float *f0 = nullptr, *f1 = nullptr, *f2 = nullptr;
    const float *c0 = nullptr, *c1 = nullptr, *c2 = nullptr;
    for (int i = 0; i < n_in; i++) {
        int s = in_sizes[i];
        const float* p = (const float*)d_in[i];
        if (s == 8 * 65536 * 32) f0 = p;
        else if (s == 8 * 32768 * 32) f1 = p;
        else if (s == 8 * 16384 * 32) f2 = p;
        else if (s == 8 * 65536 * 3) c0 = p;
        else if (s == 8 * 32768 * 3) c1 = p;
        else if (s == 8 * 16384 * 3) c2 = p;
    }

    float* out = (float*)d_out;

    k1_scatter01<<<3072, 256>>>(f0, c0, f1, c1);     // scatter s0+s1
    k2_mixed<<<K2_TOTAL, 256>>>(f2, c2, out);        // scatter s2 || transpose s0+s1
    k3_transpose2<<<12288, 256>>>(out);              // transpose s2
}